// round 10
// baseline (speedup 1.0000x reference)
#include <cuda_runtime.h>
#include <cuda_fp16.h>
#include <cstdint>

// ---------------------------------------------------------------------------
// TeamMovementModel R10: heterogeneous-pipe LSTM.
// HMMA covers K=[0,112) (7 k-tiles); K=[112,128) runs on the (idle) FMA pipe
// as fp32 FFMA2 with seq-pair-packed lanes. h[112..128) kept fp32 in a
// double-buffered side tile; slice weights pre-splatted in smem.
// Structure otherwise = R9 (fused gate ownership, 1 barrier/step).
//   92 CTAs x 16 seqs, 512 threads, fp32 c-state.
// ---------------------------------------------------------------------------

#define Hh        128
#define GATES     512
#define Tt        128
#define SEQS      16
#define NCTAS     92
#define PCTAS     88
#define NPLAYER   1408
#define NBALL     64
#define THREADS   512
#define NKT       7             // HMMA K tiles (K 0..111)
#define KOFF      112           // offloaded slice start
#define BS        136           // h tile row stride in halves
#define WS_STRIDE 66            // Ws2 per-unit stride in u64 (64 + 2 pad)

// dynamic smem (bytes)
#define OFF_XS    0
#define SZ_XS     (Tt * SEQS * 8)              // 16384
#define OFF_BSM   (OFF_XS + SZ_XS)
#define SZ_BSM    (2 * SEQS * BS * 2)          // 8704
#define OFF_WS    (OFF_BSM + SZ_BSM)           // 25088
#define SZ_WS     (128 * WS_STRIDE * 8)        // 67584
#define OFF_HS    (OFF_WS + SZ_WS)             // 92672
#define SZ_HS     (2 * 132 * 8)                // 2112
#define SM_BYTES  (OFF_HS + SZ_HS)             // 94784

__device__ float g_hid[(NPLAYER + NBALL) * Hh];

typedef unsigned long long u64;

__device__ __forceinline__ float tanhap(float x) {
    float y; asm("tanh.approx.f32 %0, %1;" : "=f"(y) : "f"(x)); return y;
}
__device__ __forceinline__ float sigap(float x) {
    return fmaf(0.5f, tanhap(0.5f * x), 0.5f);
}
__device__ __forceinline__ uint32_t h2pack(float a, float b) {
    __half2 h = __halves2half2(__float2half(a), __float2half(b));
    return *reinterpret_cast<uint32_t*>(&h);
}
__device__ __forceinline__ u64 pack2(float lo, float hi) {
    u64 r;
    asm("mov.b64 %0, {%1, %2};" : "=l"(r)
        : "r"(__float_as_uint(lo)), "r"(__float_as_uint(hi)));
    return r;
}
__device__ __forceinline__ void unpack2(u64 v, float& lo, float& hi) {
    unsigned int a, b;
    asm("mov.b64 {%0, %1}, %2;" : "=r"(a), "=r"(b) : "l"(v));
    lo = __uint_as_float(a); hi = __uint_as_float(b);
}
__device__ __forceinline__ void ffma2(u64& d, u64 a, u64 b) {
    asm("fma.rn.f32x2 %0, %1, %2, %0;" : "+l"(d) : "l"(a), "l"(b));
}

__device__ __forceinline__ void mma16816(float* d, const uint32_t* a,
                                         uint32_t b0, uint32_t b1) {
    asm volatile(
        "mma.sync.aligned.m16n8k16.row.col.f32.f16.f16.f32 "
        "{%0,%1,%2,%3}, {%4,%5,%6,%7}, {%8,%9}, {%0,%1,%2,%3};"
        : "+f"(d[0]), "+f"(d[1]), "+f"(d[2]), "+f"(d[3])
        : "r"(a[0]), "r"(a[1]), "r"(a[2]), "r"(a[3]), "r"(b0), "r"(b1));
}

__global__ __launch_bounds__(THREADS, 1)
void lstm_hmma_kernel(const float* __restrict__ xp, const float* __restrict__ xb,
                      const float* __restrict__ p_wih, const float* __restrict__ p_whh,
                      const float* __restrict__ p_bih, const float* __restrict__ p_bhh,
                      const float* __restrict__ b_wih, const float* __restrict__ b_whh,
                      const float* __restrict__ b_bih, const float* __restrict__ b_bhh)
{
    extern __shared__ unsigned char smraw[];
    float2* xs  = reinterpret_cast<float2*>(smraw + OFF_XS);   // [t][s]
    __half* Bsm = reinterpret_cast<__half*>(smraw + OFF_BSM);  // ping-pong h fp16
    u64*    Ws2 = reinterpret_cast<u64*>(smraw + OFF_WS);      // [u][k*4+g] splats
    u64*    Hs  = reinterpret_cast<u64*>(smraw + OFF_HS);      // [buf][k*8+pair] fp32x2

    const int tid = threadIdx.x;
    const int w   = tid >> 5;
    const int ln  = tid & 31;
    const int cta = blockIdx.x;
    const bool is_ball = (cta >= PCTAS);

    const float* wih_ = is_ball ? b_wih : p_wih;
    const float* whh_ = is_ball ? b_whh : p_whh;
    const float* bih_ = is_ball ? b_bih : p_bih;
    const float* bhh_ = is_ball ? b_bhh : p_bhh;
    const float* xsrc = is_ball ? xb : xp;
    const int s0    = is_ball ? (cta - PCTAS) * SEQS : cta * SEQS;
    const int gbase = is_ball ? NPLAYER + s0 : s0;

    // ---- zero h buffers (fp16 + fp32 side tiles) ----
    for (int i = tid; i < SZ_BSM / 4; i += THREADS)
        reinterpret_cast<uint32_t*>(Bsm)[i] = 0;
    for (int i = tid; i < 2 * 132; i += THREADS) Hs[i] = 0;
    // ---- stage x ----
    for (int i = tid; i < Tt * SEQS; i += THREADS) {
        int s = i >> 7, t = i & 127;
        xs[t * SEQS + s] = *reinterpret_cast<const float2*>(
            xsrc + (size_t)(s0 + s) * 256 + t * 2);
    }
    // ---- fill pre-splatted slice weights: Ws2[u][k*4+g] = splat(W[g*128+u][112+k]) ----
    for (int i = tid; i < 128 * 64; i += THREADS) {
        int uu = i >> 6, q = i & 63;
        int k = q >> 2, g = q & 3;
        float v = whh_[(size_t)(g * Hh + uu) * Hh + KOFF + k];
        Ws2[uu * WS_STRIDE + q] = pack2(v, v);
    }

    const int r0 = ln >> 2;            // 0..7
    const int c0 = (ln & 3) * 2;       // 0,2,4,6
    const int u  = w * 8 + r0;

    // ---- A fragments (K 0..111): mt0 = {i(u), f(u)}, mt1 = {g(u), o(u)} ----
    uint32_t Af[2][NKT][4];
    #pragma unroll
    for (int mt = 0; mt < 2; mt++) {
        const float* wrA = whh_ + (size_t)((mt * 2 + 0) * Hh + u) * Hh;
        const float* wrB = whh_ + (size_t)((mt * 2 + 1) * Hh + u) * Hh;
        #pragma unroll
        for (int kt = 0; kt < NKT; kt++) {
            const int k = kt * 16 + c0;
            float2 aA0 = *reinterpret_cast<const float2*>(wrA + k);
            float2 aB0 = *reinterpret_cast<const float2*>(wrB + k);
            float2 aA1 = *reinterpret_cast<const float2*>(wrA + k + 8);
            float2 aB1 = *reinterpret_cast<const float2*>(wrB + k + 8);
            Af[mt][kt][0] = h2pack(aA0.x, aA0.y);
            Af[mt][kt][1] = h2pack(aB0.x, aB0.y);
            Af[mt][kt][2] = h2pack(aA1.x, aA1.y);
            Af[mt][kt][3] = h2pack(aB1.x, aB1.y);
        }
    }

    // ---- per-gate x-weights and bias for unit u (gate order i,f,g,o) ----
    float wx0[4], wx1[4], bsr[4];
    #pragma unroll
    for (int q = 0; q < 4; q++) {
        const int g = q * Hh + u;
        wx0[q] = wih_[g * 2 + 0];
        wx1[q] = wih_[g * 2 + 1];
        bsr[q] = bih_[g] + bhh_[g];
    }

    float c[4] = {0.f, 0.f, 0.f, 0.f};
    const u64* wsu = Ws2 + u * WS_STRIDE;
    const int pr = c0 >> 1;            // seq-pair index within nt half

    __syncthreads();

    for (int t = 0; t < Tt; t++) {
        const __half* Bcur = Bsm + (t & 1) * (SEQS * BS);
        __half*       Bnxt = Bsm + ((t + 1) & 1) * (SEQS * BS);
        const u64*    Hcur = Hs + (t & 1) * 132;
        u64*          Hnxt = Hs + ((t + 1) & 1) * 132;

        // ---- acc init: bias + exact fp32 x-projection, seq-pair packed ----
        // acc[g][nt] lanes = seqs (nt*8 + c0, nt*8 + c0 + 1)
        u64 acc[4][2];
        #pragma unroll
        for (int nt = 0; nt < 2; nt++) {
            const int s = nt * 8 + c0;
            const float2 xa = xs[t * SEQS + s];
            const float2 xbv = xs[t * SEQS + s + 1];
            #pragma unroll
            for (int g = 0; g < 4; g++) {
                acc[g][nt] = pack2(
                    fmaf(wx1[g], xa.y,  fmaf(wx0[g], xa.x,  bsr[g])),
                    fmaf(wx1[g], xbv.y, fmaf(wx0[g], xbv.x, bsr[g])));
            }
        }

        // ---- FMA-pipe slice: K = 112..127, fp32 ----
        #pragma unroll
        for (int k = 0; k < 16; k++) {
            ulonglong2 wA = *reinterpret_cast<const ulonglong2*>(wsu + k * 4);
            ulonglong2 wB = *reinterpret_cast<const ulonglong2*>(wsu + k * 4 + 2);
            const u64 h0 = Hcur[k * 8 + pr];          // seqs (c0, c0+1)
            const u64 h1 = Hcur[k * 8 + 4 + pr];      // seqs (8+c0, 8+c0+1)
            ffma2(acc[0][0], h0, wA.x); ffma2(acc[0][1], h1, wA.x);
            ffma2(acc[1][0], h0, wA.y); ffma2(acc[1][1], h1, wA.y);
            ffma2(acc[2][0], h0, wB.x); ffma2(acc[2][1], h1, wB.x);
            ffma2(acc[3][0], h0, wB.y); ffma2(acc[3][1], h1, wB.y);
        }

        // ---- unpack accs into HMMA D layout ----
        // D[mt][nt][e]: e0,e1 = gate A seqs (s, s+1); e2,e3 = gate B.
        float D[2][2][4];
        #pragma unroll
        for (int nt = 0; nt < 2; nt++) {
            unpack2(acc[0][nt], D[0][nt][0], D[0][nt][1]);
            unpack2(acc[1][nt], D[0][nt][2], D[0][nt][3]);
            unpack2(acc[2][nt], D[1][nt][0], D[1][nt][1]);
            unpack2(acc[3][nt], D[1][nt][2], D[1][nt][3]);
        }

        // ---- tensor-pipe GEMM: K = 0..111 ----
        #pragma unroll
        for (int kt = 0; kt < NKT; kt++) {
            const int kh = kt * 16 + c0;
            const __half* bp0 = Bcur + r0 * BS + kh;
            const __half* bp1 = bp0 + 8 * BS;
            const uint32_t b00 = *reinterpret_cast<const uint32_t*>(bp0);
            const uint32_t b01 = *reinterpret_cast<const uint32_t*>(bp0 + 8);
            const uint32_t b10 = *reinterpret_cast<const uint32_t*>(bp1);
            const uint32_t b11 = *reinterpret_cast<const uint32_t*>(bp1 + 8);
            mma16816(D[0][0], Af[0][kt], b00, b01);
            mma16816(D[0][1], Af[0][kt], b10, b11);
            mma16816(D[1][0], Af[1][kt], b00, b01);
            mma16816(D[1][1], Af[1][kt], b10, b11);
        }

        // ---- in-register cell update; stash h for both representations ----
        float hval[4];
        #pragma unroll
        for (int j = 0; j < 4; j++) {
            const int nt = j >> 1, e1 = j & 1;
            const int m  = nt * 8 + c0 + e1;
            const float gi = sigap(D[0][nt][e1]);
            const float gf = sigap(D[0][nt][2 + e1]);
            const float gg = tanhap(D[1][nt][e1]);
            const float go = sigap(D[1][nt][2 + e1]);
            c[j] = gf * c[j] + gi * gg;
            const float h = go * tanhap(c[j]);
            hval[j] = h;
            Bnxt[m * BS + u] = __float2half(h);
        }
        // fp32 side tile for offloaded units (owned by warps 14,15)
        if (u >= KOFF) {
            const int k = u - KOFF;
            Hnxt[k * 8 + pr]     = pack2(hval[0], hval[1]);   // seqs c0, c0+1
            Hnxt[k * 8 + 4 + pr] = pack2(hval[2], hval[3]);   // seqs 8+c0, 8+c0+1
        }
        if (t == Tt - 1) {
            #pragma unroll
            for (int j = 0; j < 4; j++) {
                const int m = (j >> 1) * 8 + c0 + (j & 1);
                g_hid[(size_t)(gbase + m) * Hh + u] = hval[j];
            }
        }
        __syncthreads();
    }
}

// FC: 128 blocks = (batch b, half of 22 players). fc_w + hidden states in smem.
#define FC_THREADS 448
__global__ __launch_bounds__(FC_THREADS)
void fc_kernel(const float* __restrict__ fc_w,
               const float* __restrict__ fc_b,
               float* __restrict__ out)
{
    __shared__ float fw[40 * 258];
    __shared__ float ph[11 * 128];
    __shared__ float ball[128];

    const int bx   = blockIdx.x;
    const int b    = bx >> 1;
    const int half = bx & 1;
    const int tid  = threadIdx.x;

    for (int idx = tid; idx < 40 * 256; idx += FC_THREADS) {
        int j = idx >> 8, k = idx & 255;
        fw[j * 258 + k] = fc_w[idx];
    }
    for (int idx = tid; idx < 11 * 128; idx += FC_THREADS) {
        int p = idx >> 7, k = idx & 127;
        ph[idx] = g_hid[(b * 22 + half * 11 + p) * Hh + k];
    }
    for (int idx = tid; idx < 128; idx += FC_THREADS)
        ball[idx] = g_hid[(NPLAYER + b) * Hh + idx];
    __syncthreads();

    if (tid < 440) {
        const int p = tid / 40;
        const int j = tid - p * 40;
        const float2* php  = (const float2*)(ph + p * 128);
        const float2* blp  = (const float2*)(ball);
        const float2* fwp0 = (const float2*)(fw + j * 258);
        const float2* fwp1 = (const float2*)(fw + j * 258 + 128);
        float acc = fc_b[j];
        #pragma unroll 8
        for (int k2 = 0; k2 < 64; k2++) {
            float2 hp = php[k2], hb = blp[k2];
            float2 w0 = fwp0[k2], w1 = fwp1[k2];
            acc += hp.x * w0.x + hp.y * w0.y + hb.x * w1.x + hb.y * w1.y;
        }
        out[(b * 22 + half * 11 + p) * 40 + j] = acc;
    }
}

extern "C" void kernel_launch(void* const* d_in, const int* in_sizes, int n_in,
                              void* d_out, int out_size)
{
    const float* xp    = (const float*)d_in[0];
    const float* xb    = (const float*)d_in[1];
    const float* p_wih = (const float*)d_in[2];
    const float* p_whh = (const float*)d_in[3];
    const float* p_bih = (const float*)d_in[4];
    const float* p_bhh = (const float*)d_in[5];
    const float* b_wih = (const float*)d_in[6];
    const float* b_whh = (const float*)d_in[7];
    const float* b_bih = (const float*)d_in[8];
    const float* b_bhh = (const float*)d_in[9];
    const float* fc_w  = (const float*)d_in[10];
    const float* fc_b  = (const float*)d_in[11];
    float* out = (float*)d_out;

    cudaFuncSetAttribute(lstm_hmma_kernel,
                         cudaFuncAttributeMaxDynamicSharedMemorySize, SM_BYTES);

    lstm_hmma_kernel<<<NCTAS, THREADS, SM_BYTES>>>(xp, xb,
                                                   p_wih, p_whh, p_bih, p_bhh,
                                                   b_wih, b_whh, b_bih, b_bhh);
    fc_kernel<<<128, FC_THREADS>>>(fc_w, fc_b, out);
}

// round 11
// speedup vs baseline: 1.8143x; 1.8143x over previous
#include <cuda_runtime.h>
#include <cuda_fp16.h>
#include <cstdint>

// ---------------------------------------------------------------------------
// TeamMovementModel R11: R9 (fused gate-ownership HMMA LSTM, 1 barrier/step)
// + split even/odd-kt accumulator chains (4 -> 8 independent HMMA chains per
// warp, dependent-issue distance 4 -> 8 instructions) to expose whether R9
// was HMMA-latency-bound. R10's heterogeneous offload reverted (regression).
//   92 CTAs x 16 seqs, 512 threads, K=128 fp16, fp32 c-state.
// ---------------------------------------------------------------------------

#define Hh        128
#define GATES     512
#define Tt        128
#define SEQS      16
#define NCTAS     92
#define PCTAS     88
#define NPLAYER   1408
#define NBALL     64
#define THREADS   512
#define NKT       8             // K tiles of 16 (K=128)
#define BS        136           // h tile row stride in halves (conflict-free)

__device__ float g_hid[(NPLAYER + NBALL) * Hh];

__device__ __forceinline__ float tanhap(float x) {
    float y; asm("tanh.approx.f32 %0, %1;" : "=f"(y) : "f"(x)); return y;
}
__device__ __forceinline__ float sigap(float x) {
    return fmaf(0.5f, tanhap(0.5f * x), 0.5f);
}
__device__ __forceinline__ uint32_t h2pack(float a, float b) {
    __half2 h = __halves2half2(__float2half(a), __float2half(b));
    return *reinterpret_cast<uint32_t*>(&h);
}

// m16n8k16 row.col f32.f16.f16.f32, accumulate in place.
__device__ __forceinline__ void mma16816(float* d, const uint32_t* a,
                                         uint32_t b0, uint32_t b1) {
    asm volatile(
        "mma.sync.aligned.m16n8k16.row.col.f32.f16.f16.f32 "
        "{%0,%1,%2,%3}, {%4,%5,%6,%7}, {%8,%9}, {%0,%1,%2,%3};"
        : "+f"(d[0]), "+f"(d[1]), "+f"(d[2]), "+f"(d[3])
        : "r"(a[0]), "r"(a[1]), "r"(a[2]), "r"(a[3]), "r"(b0), "r"(b1));
}

__global__ __launch_bounds__(THREADS, 1)
void lstm_hmma_kernel(const float* __restrict__ xp, const float* __restrict__ xb,
                      const float* __restrict__ p_wih, const float* __restrict__ p_whh,
                      const float* __restrict__ p_bih, const float* __restrict__ p_bhh,
                      const float* __restrict__ b_wih, const float* __restrict__ b_whh,
                      const float* __restrict__ b_bih, const float* __restrict__ b_bhh)
{
    __shared__ float2 xs[Tt * SEQS];              // [t][s]     16 KB
    __shared__ __half Bsm[2 * SEQS * BS];         // ping-pong h tiles, 8.5 KB

    const int tid = threadIdx.x;
    const int w   = tid >> 5;          // 0..15 -> units [8w, 8w+8)
    const int ln  = tid & 31;
    const int cta = blockIdx.x;
    const bool is_ball = (cta >= PCTAS);

    const float* wih_ = is_ball ? b_wih : p_wih;
    const float* whh_ = is_ball ? b_whh : p_whh;
    const float* bih_ = is_ball ? b_bih : p_bih;
    const float* bhh_ = is_ball ? b_bhh : p_bhh;
    const float* xsrc = is_ball ? xb : xp;
    const int s0    = is_ball ? (cta - PCTAS) * SEQS : cta * SEQS;
    const int gbase = is_ball ? NPLAYER + s0 : s0;

    // ---- zero both h buffers, stage x ----
    for (int i = tid; i < 2 * SEQS * BS / 2; i += THREADS)
        reinterpret_cast<uint32_t*>(Bsm)[i] = 0;
    for (int i = tid; i < Tt * SEQS; i += THREADS) {
        int s = i >> 7, t = i & 127;
        xs[t * SEQS + s] = *reinterpret_cast<const float2*>(
            xsrc + (size_t)(s0 + s) * 256 + t * 2);
    }

    const int r0 = ln >> 2;            // 0..7
    const int c0 = (ln & 3) * 2;       // 0,2,4,6
    const int u  = w * 8 + r0;         // hidden unit owned by this thread

    // ---- A fragments: mt0 rows = {i(u), f(u)}, mt1 rows = {g(u), o(u)} ----
    uint32_t Af[2][NKT][4];
    #pragma unroll
    for (int mt = 0; mt < 2; mt++) {
        const float* wrA = whh_ + (size_t)((mt * 2 + 0) * Hh + u) * Hh;  // i or g
        const float* wrB = whh_ + (size_t)((mt * 2 + 1) * Hh + u) * Hh;  // f or o
        #pragma unroll
        for (int kt = 0; kt < NKT; kt++) {
            const int k = kt * 16 + c0;
            float2 aA0 = *reinterpret_cast<const float2*>(wrA + k);
            float2 aB0 = *reinterpret_cast<const float2*>(wrB + k);
            float2 aA1 = *reinterpret_cast<const float2*>(wrA + k + 8);
            float2 aB1 = *reinterpret_cast<const float2*>(wrB + k + 8);
            Af[mt][kt][0] = h2pack(aA0.x, aA0.y);
            Af[mt][kt][1] = h2pack(aB0.x, aB0.y);
            Af[mt][kt][2] = h2pack(aA1.x, aA1.y);
            Af[mt][kt][3] = h2pack(aB1.x, aB1.y);
        }
    }

    // ---- per-gate x-weights and bias for unit u ----
    float wx0[4], wx1[4], bsr[4];
    #pragma unroll
    for (int q = 0; q < 4; q++) {
        const int g = q * Hh + u;
        wx0[q] = wih_[g * 2 + 0];
        wx1[q] = wih_[g * 2 + 1];
        bsr[q] = bih_[g] + bhh_[g];
    }

    float c[4] = {0.f, 0.f, 0.f, 0.f};

    __syncthreads();

    for (int t = 0; t < Tt; t++) {
        const __half* Bcur = Bsm + (t & 1) * (SEQS * BS);
        __half*       Bnxt = Bsm + ((t + 1) & 1) * (SEQS * BS);

        // ---- D init: bias + exact fp32 x-projection; E = 0 (odd-kt partials) ----
        float D[2][2][4], E[2][2][4];
        #pragma unroll
        for (int nt = 0; nt < 2; nt++) {
            #pragma unroll
            for (int e1 = 0; e1 < 2; e1++) {
                const int s = nt * 8 + c0 + e1;
                const float2 x = xs[t * SEQS + s];
                D[0][nt][e1]     = fmaf(wx1[0], x.y, fmaf(wx0[0], x.x, bsr[0]));
                D[0][nt][2 + e1] = fmaf(wx1[1], x.y, fmaf(wx0[1], x.x, bsr[1]));
                D[1][nt][e1]     = fmaf(wx1[2], x.y, fmaf(wx0[2], x.x, bsr[2]));
                D[1][nt][2 + e1] = fmaf(wx1[3], x.y, fmaf(wx0[3], x.x, bsr[3]));
            }
        }
        #pragma unroll
        for (int mt = 0; mt < 2; mt++)
            #pragma unroll
            for (int nt = 0; nt < 2; nt++)
                #pragma unroll
                for (int e = 0; e < 4; e++) E[mt][nt][e] = 0.0f;

        // ---- recurrent GEMM over h: even kt -> D chains, odd kt -> E chains ----
        #pragma unroll
        for (int kt = 0; kt < NKT; kt++) {
            const int kh = kt * 16 + c0;
            const __half* bp0 = Bcur + r0 * BS + kh;
            const __half* bp1 = bp0 + 8 * BS;
            const uint32_t b00 = *reinterpret_cast<const uint32_t*>(bp0);
            const uint32_t b01 = *reinterpret_cast<const uint32_t*>(bp0 + 8);
            const uint32_t b10 = *reinterpret_cast<const uint32_t*>(bp1);
            const uint32_t b11 = *reinterpret_cast<const uint32_t*>(bp1 + 8);
            float (*T)[2][4] = (kt & 1) ? E : D;
            mma16816(T[0][0], Af[0][kt], b00, b01);
            mma16816(T[0][1], Af[0][kt], b10, b11);
            mma16816(T[1][0], Af[1][kt], b00, b01);
            mma16816(T[1][1], Af[1][kt], b10, b11);
        }

        // ---- merge partials + in-register LSTM cell update ----
        #pragma unroll
        for (int j = 0; j < 4; j++) {
            const int nt = j >> 1, e1 = j & 1;
            const int m  = nt * 8 + c0 + e1;
            const float gi = sigap(D[0][nt][e1]     + E[0][nt][e1]);
            const float gf = sigap(D[0][nt][2 + e1] + E[0][nt][2 + e1]);
            const float gg = tanhap(D[1][nt][e1]     + E[1][nt][e1]);
            const float go = sigap(D[1][nt][2 + e1] + E[1][nt][2 + e1]);
            c[j] = gf * c[j] + gi * gg;
            const float h = go * tanhap(c[j]);
            Bnxt[m * BS + u] = __float2half(h);
            if (t == Tt - 1)
                g_hid[(size_t)(gbase + m) * Hh + u] = h;
        }
        __syncthreads();   // h(t+1) visible before anyone reads Bnxt
    }
}

// FC: 128 blocks = (batch b, half of 22 players). fc_w + hidden states in smem.
#define FC_THREADS 448
__global__ __launch_bounds__(FC_THREADS)
void fc_kernel(const float* __restrict__ fc_w,
               const float* __restrict__ fc_b,
               float* __restrict__ out)
{
    __shared__ float fw[40 * 258];
    __shared__ float ph[11 * 128];
    __shared__ float ball[128];

    const int bx   = blockIdx.x;
    const int b    = bx >> 1;
    const int half = bx & 1;
    const int tid  = threadIdx.x;

    for (int idx = tid; idx < 40 * 256; idx += FC_THREADS) {
        int j = idx >> 8, k = idx & 255;
        fw[j * 258 + k] = fc_w[idx];
    }
    for (int idx = tid; idx < 11 * 128; idx += FC_THREADS) {
        int p = idx >> 7, k = idx & 127;
        ph[idx] = g_hid[(b * 22 + half * 11 + p) * Hh + k];
    }
    for (int idx = tid; idx < 128; idx += FC_THREADS)
        ball[idx] = g_hid[(NPLAYER + b) * Hh + idx];
    __syncthreads();

    if (tid < 440) {
        const int p = tid / 40;
        const int j = tid - p * 40;
        const float2* php  = (const float2*)(ph + p * 128);
        const float2* blp  = (const float2*)(ball);
        const float2* fwp0 = (const float2*)(fw + j * 258);
        const float2* fwp1 = (const float2*)(fw + j * 258 + 128);
        float acc = fc_b[j];
        #pragma unroll 8
        for (int k2 = 0; k2 < 64; k2++) {
            float2 hp = php[k2], hb = blp[k2];
            float2 w0 = fwp0[k2], w1 = fwp1[k2];
            acc += hp.x * w0.x + hp.y * w0.y + hb.x * w1.x + hb.y * w1.y;
        }
        out[(b * 22 + half * 11 + p) * 40 + j] = acc;
    }
}

extern "C" void kernel_launch(void* const* d_in, const int* in_sizes, int n_in,
                              void* d_out, int out_size)
{
    const float* xp    = (const float*)d_in[0];
    const float* xb    = (const float*)d_in[1];
    const float* p_wih = (const float*)d_in[2];
    const float* p_whh = (const float*)d_in[3];
    const float* p_bih = (const float*)d_in[4];
    const float* p_bhh = (const float*)d_in[5];
    const float* b_wih = (const float*)d_in[6];
    const float* b_whh = (const float*)d_in[7];
    const float* b_bih = (const float*)d_in[8];
    const float* b_bhh = (const float*)d_in[9];
    const float* fc_w  = (const float*)d_in[10];
    const float* fc_b  = (const float*)d_in[11];
    float* out = (float*)d_out;

    lstm_hmma_kernel<<<NCTAS, THREADS>>>(xp, xb,
                                         p_wih, p_whh, p_bih, p_bhh,
                                         b_wih, b_whh, b_bih, b_bhh);
    fc_kernel<<<128, FC_THREADS>>>(fc_w, fc_b, out);
}